// round 10
// baseline (speedup 1.0000x reference)
#include <cuda_runtime.h>
#include <cuda_bf16.h>
#include <cstdint>

// Problem constants (B=2, S=2048, D=512, K=64)
#define PB 2
#define PS 2048
#define PD 512
#define PK 64
#define MT (PB * PS)   // 4096 rows total

// ---------------------------------------------------------------------------
// Scratch (device globals — no allocation allowed)
// ---------------------------------------------------------------------------
__device__ __align__(16) __nv_bfloat16 g_x_bf[MT * PD];    // bf16(x)
__device__ __align__(16) __nv_bfloat16 g_h_bf[MT * PD];    // bf16(h)
__device__ __align__(16) __nv_bfloat16 g_f_bf[MT * PD];    // bf16(fused)
__device__ __align__(16) __nv_bfloat16 g_wi_hi[PD * PD];
__device__ __align__(16) __nv_bfloat16 g_wi_lo[PD * PD];
__device__ __align__(16) __nv_bfloat16 g_wo_hi[PD * PD];
__device__ __align__(16) __nv_bfloat16 g_wo_lo[PD * PD];

// ---------------------------------------------------------------------------
// PTX helpers (sm_80/sm_100-level only — harness compiles via compute_103 PTX,
// which rejects 'a'-gated tcgen05/TMEM; f32x2 packed math is plain sm_100+)
// ---------------------------------------------------------------------------
__device__ __forceinline__ uint32_t smem_u32(const void* p) {
    uint32_t a;
    asm("{ .reg .u64 t; cvta.to.shared.u64 t, %1; cvt.u32.u64 %0, t; }" : "=r"(a) : "l"(p));
    return a;
}

#define LDSM4(r, addr) \
    asm volatile("ldmatrix.sync.aligned.m8n8.x4.shared.b16 {%0,%1,%2,%3}, [%4];" \
                 : "=r"((r)[0]), "=r"((r)[1]), "=r"((r)[2]), "=r"((r)[3]) : "r"(addr))

#define MMA16816(d, a, b0, b1) \
    asm volatile("mma.sync.aligned.m16n8k16.row.col.f32.bf16.bf16.f32 " \
                 "{%0,%1,%2,%3}, {%4,%5,%6,%7}, {%8,%9}, {%0,%1,%2,%3};" \
                 : "+f"((d)[0]), "+f"((d)[1]), "+f"((d)[2]), "+f"((d)[3]) \
                 : "r"((a)[0]), "r"((a)[1]), "r"((a)[2]), "r"((a)[3]), "r"(b0), "r"(b1))

#define CP16(dst, src) \
    asm volatile("cp.async.cg.shared.global [%0], [%1], 16;" :: "r"(dst), "l"(src))
#define CP_COMMIT()  asm volatile("cp.async.commit_group;" ::: "memory")
#define CP_WAIT(N)   asm volatile("cp.async.wait_group %0;" :: "n"(N) : "memory")

// Packed bf16x2-word -> f32x2 convert + packed FMA:  acc(f32x2) += wk2 * {lo,hi}
#define CVT_FMA2(acc, u, wk2) \
    asm("{\n\t" \
        ".reg .b32 lo, hi;\n\t" \
        ".reg .b64 val;\n\t" \
        "shl.b32 lo, %1, 16;\n\t" \
        "and.b32 hi, %1, 0xFFFF0000;\n\t" \
        "mov.b64 val, {lo, hi};\n\t" \
        "fma.rn.f32x2 %0, %2, val, %0;\n\t" \
        "}" : "+l"(acc) : "r"(u), "l"(wk2))

// ---------------------------------------------------------------------------
// GEMM (NT): C[m,n] = sum_k A[m,k]*B[n,k]
//   A: plain bf16.  B ~ Bhi + Blo (split).  C = A*Bhi + A*Blo, fp32 acc.
// Tile 128x64, BK=32, 8 warps (4m x 2n), 4-stage cp.async ring, 2 CTAs/SM.
// All chunk LDSMs hoisted before the MMA block (latency batching).
// EPI: residual tile prefetched to smem with the prologue cp.async group.
// ---------------------------------------------------------------------------
#define GBM 128
#define GBN 64
#define GBK 32
#define NITER (PD / GBK)       // 16
#define STAGES 4
#define ATILEB (128 * 64)      // 8192 B
#define BTILEB (64 * 64)       // 4096 B
#define STAGEB (ATILEB + 2 * BTILEB)   // 16384 B
#define GEMM_SMEM (STAGES * STAGEB)    // 65536 B
#define RESB (GBM * GBN * 4)           // 32768 B residual tile
#define EPI_SMEM (GEMM_SMEM + RESB)    // 98304 B

__device__ __forceinline__ uint32_t swz(int row, int u) {
    return (uint32_t)(row * 64 + ((u ^ ((row >> 1) & 3)) * 16));
}

// OBF16: write C as bf16 to Cb (no epilogue). Else fp32 to Cf with bias+resid if EPI.
template <bool EPI, bool OBF16>
__global__ __launch_bounds__(256, 2)
void mma_gemm_kernel(const __nv_bfloat16* __restrict__ A,
                     const __nv_bfloat16* __restrict__ Bhi, const __nv_bfloat16* __restrict__ Blo,
                     float* __restrict__ Cf, __nv_bfloat16* __restrict__ Cb,
                     const float* __restrict__ bias, const float* __restrict__ resid)
{
    extern __shared__ __align__(128) char sm[];
    const uint32_t sbase = smem_u32(sm);

    const int tid  = threadIdx.x;
    const int lane = tid & 31;
    const int wid  = tid >> 5;
    const int warpM = (wid & 3) * 32;
    const int warpN = (wid >> 2) * 32;
    const int blockM = blockIdx.y * GBM;
    const int blockN = blockIdx.x * GBN;

    // cp.async mapping
    const int arow = tid >> 1;
    const int au   = (tid & 1) * 2;
    const uint32_t acd0 = swz(arow, au);
    const uint32_t acd1 = swz(arow, au + 1);
    const size_t aoff = (size_t)(blockM + arow) * PD + au * 8;
    const int brow = tid >> 2;
    const int bu   = tid & 3;
    const uint32_t bcd = swz(brow, bu);
    const size_t boff = (size_t)(blockN + brow) * PD + bu * 8;

    // ldmatrix lane mapping (fragment layout identical to proven R4-R9 kernels)
    const int mx = lane >> 3;
    const int lr = lane & 7;
    const int rA = (mx & 1) * 8 + lr;
    const int uA = mx >> 1;
    const int rB = (mx >> 1) * 8 + lr;
    const int uB = mx & 1;
    const uint32_t offA0 = (uint32_t)(warpM + rA) * 64 + ((0 + uA) ^ ((rA >> 1) & 3)) * 16;
    const uint32_t offA1 = (uint32_t)(warpM + rA) * 64 + ((2 + uA) ^ ((rA >> 1) & 3)) * 16;
    const uint32_t offB0 = (uint32_t)(warpN + rB) * 64 + ((0 + uB) ^ ((rB >> 1) & 3)) * 16;
    const uint32_t offB1 = (uint32_t)(warpN + rB) * 64 + ((2 + uB) ^ ((rB >> 1) & 3)) * 16;

    float acc[2][4][4];
#pragma unroll
    for (int mt = 0; mt < 2; mt++)
#pragma unroll
        for (int nt = 0; nt < 4; nt++)
#pragma unroll
            for (int j = 0; j < 4; j++) acc[mt][nt][j] = 0.0f;

    auto issue = [&](int chunk, int stage) {
        const int kt = chunk * GBK;
        const uint32_t sd = sbase + stage * STAGEB;
        CP16(sd + acd0, A + aoff + kt);
        CP16(sd + acd1, A + aoff + kt + 8);
        CP16(sd + ATILEB + bcd, Bhi + boff + kt);
        CP16(sd + ATILEB + BTILEB + bcd, Blo + boff + kt);
    };

    // prologue: residual prefetch (EPI) rides the first commit group
    if (EPI) {
        // 2048 16B-units; 8 per thread. unit = row*16 + c4 (64 fp32 = 16 units/row)
#pragma unroll
        for (int j = 0; j < 8; j++) {
            const int unit = tid * 8 + j;
            const int row = unit >> 4;
            const int c4  = unit & 15;
            CP16(sbase + GEMM_SMEM + unit * 16,
                 resid + (size_t)(blockM + row) * PD + blockN + c4 * 4);
        }
    }
    issue(0, 0); CP_COMMIT();
    issue(1, 1); CP_COMMIT();
    issue(2, 2); CP_COMMIT();

    for (int c = 0; c < NITER; c++) {
        CP_WAIT(2);
        __syncthreads();

        if (c + 3 < NITER) issue(c + 3, (c + 3) & 3);
        CP_COMMIT();

        const uint32_t sb = sbase + (c & 3) * STAGEB;

        // ---- hoist ALL LDSMs for this chunk (batched latency) ----
        uint32_t ah[2][2][4], bh[2][2][4], bl[2][2][4];
#pragma unroll
        for (int hk = 0; hk < 2; hk++) {
            const uint32_t oA = hk ? offA1 : offA0;
            const uint32_t oB = hk ? offB1 : offB0;
#pragma unroll
            for (int mt = 0; mt < 2; mt++)
                LDSM4(ah[hk][mt], sb + oA + mt * 1024);
#pragma unroll
            for (int np = 0; np < 2; np++) {
                LDSM4(bh[hk][np], sb + ATILEB + oB + np * 1024);
                LDSM4(bl[hk][np], sb + ATILEB + BTILEB + oB + np * 1024);
            }
        }
        // ---- uninterrupted MMA stream ----
#pragma unroll
        for (int hk = 0; hk < 2; hk++) {
#pragma unroll
            for (int np = 0; np < 2; np++) {
#pragma unroll
                for (int sub = 0; sub < 2; sub++) {
                    const int nt = np * 2 + sub;
                    const uint32_t b0h = bh[hk][np][sub * 2], b1h = bh[hk][np][sub * 2 + 1];
                    const uint32_t b0l = bl[hk][np][sub * 2], b1l = bl[hk][np][sub * 2 + 1];
#pragma unroll
                    for (int mt = 0; mt < 2; mt++) {
                        MMA16816(acc[mt][nt], ah[hk][mt], b0h, b1h);
                        MMA16816(acc[mt][nt], ah[hk][mt], b0l, b1l);
                    }
                }
            }
        }
        __syncthreads();
    }

    // --- epilogue ---
    const int g  = lane >> 2;
    const int tg = lane & 3;
    const float* rsm = (const float*)(sm + GEMM_SMEM);
#pragma unroll
    for (int mt = 0; mt < 2; mt++) {
#pragma unroll
        for (int nt = 0; nt < 4; nt++) {
            const int rl = warpM + mt * 16 + g;            // local row 0..127
            const int cl = warpN + nt * 8 + tg * 2;        // local col 0..63
            const int row = blockM + rl;
            const int col = blockN + cl;
            const size_t o0 = (size_t)row * PD + col;
            const size_t o1 = (size_t)(row + 8) * PD + col;
            if (OBF16) {
                *(__nv_bfloat162*)&Cb[o0] = __floats2bfloat162_rn(acc[mt][nt][0], acc[mt][nt][1]);
                *(__nv_bfloat162*)&Cb[o1] = __floats2bfloat162_rn(acc[mt][nt][2], acc[mt][nt][3]);
            } else {
                float2 v0 = make_float2(acc[mt][nt][0], acc[mt][nt][1]);
                float2 v1 = make_float2(acc[mt][nt][2], acc[mt][nt][3]);
                if (EPI) {
                    const float2 bb = *(const float2*)&bias[col];
                    const float2 x0 = *(const float2*)&rsm[rl * 64 + cl];
                    const float2 x1 = *(const float2*)&rsm[(rl + 8) * 64 + cl];
                    v0.x += bb.x + x0.x; v0.y += bb.y + x0.y;
                    v1.x += bb.x + x1.x; v1.y += bb.y + x1.y;
                }
                *(float2*)&Cf[o0] = v0;
                *(float2*)&Cf[o1] = v1;
            }
        }
    }
}

// ---------------------------------------------------------------------------
// Prep: x -> bf16; W_in, W_out -> (hi, lo) split. One launch.
// ---------------------------------------------------------------------------
#define NX (MT * PD)      // 2097152
#define NW (PD * PD)      // 262144
#define PREP_THREADS ((NX + 2 * NW) / 4)

__device__ __forceinline__ void split4(const float* src, __nv_bfloat16* hi,
                                       __nv_bfloat16* lo, int i)
{
    const float4 v = *(const float4*)(src + i);
    float vv[4] = {v.x, v.y, v.z, v.w};
    __align__(8) __nv_bfloat16 h4[4], l4[4];
#pragma unroll
    for (int j = 0; j < 4; j++) {
        h4[j] = __float2bfloat16(vv[j]);
        l4[j] = __float2bfloat16(vv[j] - __bfloat162float(h4[j]));
    }
    *(uint2*)(hi + i) = *(const uint2*)h4;
    *(uint2*)(lo + i) = *(const uint2*)l4;
}

__global__ __launch_bounds__(256)
void prep_kernel(const float* __restrict__ x,  __nv_bfloat16* __restrict__ xb,
                 const float* __restrict__ Wi, __nv_bfloat16* __restrict__ wih, __nv_bfloat16* __restrict__ wil,
                 const float* __restrict__ Wo, __nv_bfloat16* __restrict__ woh, __nv_bfloat16* __restrict__ wol)
{
    const int t = blockIdx.x * blockDim.x + threadIdx.x;
    const int i = t * 4;
    if (i < NX) {
        const float4 v = *(const float4*)(x + i);
        __align__(8) __nv_bfloat16 h4[4];
        h4[0] = __float2bfloat16(v.x);
        h4[1] = __float2bfloat16(v.y);
        h4[2] = __float2bfloat16(v.z);
        h4[3] = __float2bfloat16(v.w);
        *(uint2*)(xb + i) = *(const uint2*)h4;
    } else if (i < NX + NW) {
        split4(Wi, wih, wil, i - NX);
    } else {
        split4(Wo, woh, wol, i - NX - NW);
    }
}

// ---------------------------------------------------------------------------
// Fused softmax + gather-fuse (unchanged from R9):
//   w[s,:] = softmax_k(-dist[s, routes[s,k]])  (warp 0 per block)
//   fused[b,s,:] = sum_k w[s,k] * h[b, routes[s,k], :]   (bf16 out)
// ---------------------------------------------------------------------------
__global__ __launch_bounds__(128)
void fuse_kernel(const __nv_bfloat16* __restrict__ h, const int* __restrict__ routes,
                 const float* __restrict__ dist, __nv_bfloat16* __restrict__ f)
{
    const int s   = blockIdx.x;
    const int tid = threadIdx.x;

    __shared__ __align__(8) uint2 wr[PK];   // .x = row*PD*2 (bytes), .y = w bits

    if (tid < 32) {
        const int lane = tid;
        const int r0 = routes[s * PK + lane];
        const int r1 = routes[s * PK + lane + 32];
        const float v0 = -dist[(size_t)s * PS + r0];
        const float v1 = -dist[(size_t)s * PS + r1];

        float m = fmaxf(v0, v1);
#pragma unroll
        for (int off = 16; off > 0; off >>= 1)
            m = fmaxf(m, __shfl_xor_sync(0xFFFFFFFFu, m, off));

        const float e0 = __expf(v0 - m);
        const float e1 = __expf(v1 - m);
        float sum = e0 + e1;
#pragma unroll
        for (int off = 16; off > 0; off >>= 1)
            sum += __shfl_xor_sync(0xFFFFFFFFu, sum, off);
        const float inv = 1.0f / sum;

        wr[lane]      = make_uint2((uint32_t)r0 * (PD * 2), __float_as_uint(e0 * inv));
        wr[lane + 32] = make_uint2((uint32_t)r1 * (PD * 2), __float_as_uint(e1 * inv));
    }
    __syncthreads();

    const int b = tid >> 6;
    const int t = tid & 63;
    const char* hb = (const char*)(h + (size_t)b * PS * PD) + t * 16;

    uint64_t a0 = 0, a1 = 0, a2 = 0, a3 = 0;

#pragma unroll
    for (int k = 0; k < PK; k++) {
        const uint2 e = wr[k];
        const uint4 v = *(const uint4*)(hb + e.x);
        uint64_t wk2;
        asm("mov.b64 %0, {%1, %1};" : "=l"(wk2) : "r"(e.y));
        CVT_FMA2(a0, v.x, wk2);
        CVT_FMA2(a1, v.y, wk2);
        CVT_FMA2(a2, v.z, wk2);
        CVT_FMA2(a3, v.w, wk2);
    }

    float r0, r1, r2, r3, r4, r5, r6, r7;
    asm("mov.b64 {%0, %1}, %2;" : "=f"(r0), "=f"(r1) : "l"(a0));
    asm("mov.b64 {%0, %1}, %2;" : "=f"(r2), "=f"(r3) : "l"(a1));
    asm("mov.b64 {%0, %1}, %2;" : "=f"(r4), "=f"(r5) : "l"(a2));
    asm("mov.b64 {%0, %1}, %2;" : "=f"(r6), "=f"(r7) : "l"(a3));

    __align__(16) __nv_bfloat162 o[4];
    o[0] = __floats2bfloat162_rn(r0, r1);
    o[1] = __floats2bfloat162_rn(r2, r3);
    o[2] = __floats2bfloat162_rn(r4, r5);
    o[3] = __floats2bfloat162_rn(r6, r7);
    *(uint4*)&f[((size_t)b * PS + s) * PD + t * 8] = *(const uint4*)o;
}

// ---------------------------------------------------------------------------
// kernel_launch
// Inputs: 0: x (B,S,D) f32 | 1: routes (S,K) i32 | 2: distances (S,S) f32
//         3: W_in (D,D) f32 | 4: W_out (D,D) f32 | 5: b_out (D,) f32
// ---------------------------------------------------------------------------
extern "C" void kernel_launch(void* const* d_in, const int* in_sizes, int n_in,
                              void* d_out, int out_size)
{
    const float* x      = (const float*)d_in[0];
    const int*   routes = (const int*)  d_in[1];
    const float* dist   = (const float*)d_in[2];
    const float* W_in   = (const float*)d_in[3];
    const float* W_out  = (const float*)d_in[4];
    const float* b_out  = (const float*)d_in[5];
    float*       out    = (float*)d_out;

    __nv_bfloat16 *xb, *hb, *fb, *wih, *wil, *woh, *wol;
    cudaGetSymbolAddress((void**)&xb,  g_x_bf);
    cudaGetSymbolAddress((void**)&hb,  g_h_bf);
    cudaGetSymbolAddress((void**)&fb,  g_f_bf);
    cudaGetSymbolAddress((void**)&wih, g_wi_hi);
    cudaGetSymbolAddress((void**)&wil, g_wi_lo);
    cudaGetSymbolAddress((void**)&woh, g_wo_hi);
    cudaGetSymbolAddress((void**)&wol, g_wo_lo);

    static bool attr_set = false;
    if (!attr_set) {
        cudaFuncSetAttribute((const void*)mma_gemm_kernel<false, true>,
                             cudaFuncAttributeMaxDynamicSharedMemorySize, GEMM_SMEM);
        cudaFuncSetAttribute((const void*)mma_gemm_kernel<true, false>,
                             cudaFuncAttributeMaxDynamicSharedMemorySize, EPI_SMEM);
        attr_set = true;
    }

    // 0) prep: x->bf16, W splits
    prep_kernel<<<PREP_THREADS / 256, 256>>>(x, xb, W_in, wih, wil, W_out, woh, wol);

    // 1) h = x @ W_in^T  (bf16 out)
    {
        dim3 grid(PD / GBN, MT / GBM);   // 8 x 32 = 256 CTAs, 2/SM
        mma_gemm_kernel<false, true><<<grid, 256, GEMM_SMEM>>>(xb, wih, wil, nullptr, hb, nullptr, nullptr);
    }

    // 2) softmax + gather-fuse -> bf16 fused (one kernel)
    fuse_kernel<<<PS, 128>>>(hb, routes, dist, fb);

    // 3) out = fused @ W_out^T + b_out + x  (resid prefetched to smem)
    {
        dim3 grid(PD / GBN, MT / GBM);
        mma_gemm_kernel<true, false><<<grid, 256, EPI_SMEM>>>(fb, woh, wol, out, nullptr, b_out, x);
    }
}

// round 11
// speedup vs baseline: 1.1223x; 1.1223x over previous
#include <cuda_runtime.h>
#include <cuda_bf16.h>
#include <cstdint>

// Problem constants (B=2, S=2048, D=512, K=64)
#define PB 2
#define PS 2048
#define PD 512
#define PK 64
#define MT (PB * PS)   // 4096 rows total

// ---------------------------------------------------------------------------
// Scratch (device globals — no allocation allowed)
// ---------------------------------------------------------------------------
__device__ __align__(16) __nv_bfloat16 g_x_bf[MT * PD];    // bf16(x)
__device__ __align__(16) __nv_bfloat16 g_h_bf[MT * PD];    // bf16(h)
__device__ __align__(16) __nv_bfloat16 g_f_bf[MT * PD];    // bf16(fused)
__device__ __align__(16) __nv_bfloat16 g_wi_hi[PD * PD];
__device__ __align__(16) __nv_bfloat16 g_wo_hi[PD * PD];
__device__ __align__(16) __nv_bfloat16 g_wo_lo[PD * PD];

// ---------------------------------------------------------------------------
// PTX helpers (sm_80/sm_100-level only — harness compiles via compute_103 PTX,
// which rejects 'a'-gated tcgen05/TMEM; f32x2 packed math is plain sm_100+)
// ---------------------------------------------------------------------------
__device__ __forceinline__ uint32_t smem_u32(const void* p) {
    uint32_t a;
    asm("{ .reg .u64 t; cvta.to.shared.u64 t, %1; cvt.u32.u64 %0, t; }" : "=r"(a) : "l"(p));
    return a;
}

#define LDSM4(r, addr) \
    asm volatile("ldmatrix.sync.aligned.m8n8.x4.shared.b16 {%0,%1,%2,%3}, [%4];" \
                 : "=r"((r)[0]), "=r"((r)[1]), "=r"((r)[2]), "=r"((r)[3]) : "r"(addr))

#define MMA16816(d, a, b0, b1) \
    asm volatile("mma.sync.aligned.m16n8k16.row.col.f32.bf16.bf16.f32 " \
                 "{%0,%1,%2,%3}, {%4,%5,%6,%7}, {%8,%9}, {%0,%1,%2,%3};" \
                 : "+f"((d)[0]), "+f"((d)[1]), "+f"((d)[2]), "+f"((d)[3]) \
                 : "r"((a)[0]), "r"((a)[1]), "r"((a)[2]), "r"((a)[3]), "r"(b0), "r"(b1))

#define CP16(dst, src) \
    asm volatile("cp.async.cg.shared.global [%0], [%1], 16;" :: "r"(dst), "l"(src))
#define CP_COMMIT()  asm volatile("cp.async.commit_group;" ::: "memory")
#define CP_WAIT(N)   asm volatile("cp.async.wait_group %0;" :: "n"(N) : "memory")

// Packed bf16x2-word -> f32x2 convert + packed FMA:  acc(f32x2) += wk2 * {lo,hi}
#define CVT_FMA2(acc, u, wk2) \
    asm("{\n\t" \
        ".reg .b32 lo, hi;\n\t" \
        ".reg .b64 val;\n\t" \
        "shl.b32 lo, %1, 16;\n\t" \
        "and.b32 hi, %1, 0xFFFF0000;\n\t" \
        "mov.b64 val, {lo, hi};\n\t" \
        "fma.rn.f32x2 %0, %2, val, %0;\n\t" \
        "}" : "+l"(acc) : "r"(u), "l"(wk2))

// ---------------------------------------------------------------------------
// GEMM (NT): C[m,n] = sum_k A[m,k]*B[n,k]
//   A: plain bf16.  SPLITB: B ~ Bhi + Blo (2 MMA terms); else B = Bhi only.
// Tile 128x64, BK=32, 8 warps (4m x 2n), 4-stage cp.async ring, 2 CTAs/SM.
// R9-proven interleaved LDSM/MMA mainloop (R10 hoist reverted).
// smem row = 64B; swizzle u' = u ^ ((row>>1)&3)
// ---------------------------------------------------------------------------
#define GBM 128
#define GBN 64
#define GBK 32
#define NITER (PD / GBK)       // 16
#define STAGES 4
#define ATILEB (128 * 64)      // 8192 B
#define BTILEB (64 * 64)       // 4096 B

__device__ __forceinline__ uint32_t swz(int row, int u) {
    return (uint32_t)(row * 64 + ((u ^ ((row >> 1) & 3)) * 16));
}

// OBF16: write C as bf16 to Cb (no epilogue). Else fp32 to Cf with bias+resid if EPI.
template <bool EPI, bool OBF16, bool SPLITB>
__global__ __launch_bounds__(256, 2)
void mma_gemm_kernel(const __nv_bfloat16* __restrict__ A,
                     const __nv_bfloat16* __restrict__ Bhi, const __nv_bfloat16* __restrict__ Blo,
                     float* __restrict__ Cf, __nv_bfloat16* __restrict__ Cb,
                     const float* __restrict__ bias, const float* __restrict__ resid)
{
    constexpr int STAGEB = ATILEB + (SPLITB ? 2 : 1) * BTILEB;

    extern __shared__ __align__(128) char sm[];
    const uint32_t sbase = smem_u32(sm);

    const int tid  = threadIdx.x;
    const int lane = tid & 31;
    const int wid  = tid >> 5;
    const int warpM = (wid & 3) * 32;
    const int warpN = (wid >> 2) * 32;
    const int blockM = blockIdx.y * GBM;
    const int blockN = blockIdx.x * GBN;

    // cp.async mapping
    const int arow = tid >> 1;
    const int au   = (tid & 1) * 2;
    const uint32_t acd0 = swz(arow, au);
    const uint32_t acd1 = swz(arow, au + 1);
    const size_t aoff = (size_t)(blockM + arow) * PD + au * 8;
    const int brow = tid >> 2;
    const int bu   = tid & 3;
    const uint32_t bcd = swz(brow, bu);
    const size_t boff = (size_t)(blockN + brow) * PD + bu * 8;

    // ldmatrix lane mapping (fragment layout identical to proven R4-R9 kernels)
    const int mx = lane >> 3;
    const int lr = lane & 7;
    const int rA = (mx & 1) * 8 + lr;
    const int uA = mx >> 1;
    const int rB = (mx >> 1) * 8 + lr;
    const int uB = mx & 1;
    const uint32_t offA0 = (uint32_t)(warpM + rA) * 64 + ((0 + uA) ^ ((rA >> 1) & 3)) * 16;
    const uint32_t offA1 = (uint32_t)(warpM + rA) * 64 + ((2 + uA) ^ ((rA >> 1) & 3)) * 16;
    const uint32_t offB0 = (uint32_t)(warpN + rB) * 64 + ((0 + uB) ^ ((rB >> 1) & 3)) * 16;
    const uint32_t offB1 = (uint32_t)(warpN + rB) * 64 + ((2 + uB) ^ ((rB >> 1) & 3)) * 16;

    float acc[2][4][4];
#pragma unroll
    for (int mt = 0; mt < 2; mt++)
#pragma unroll
        for (int nt = 0; nt < 4; nt++)
#pragma unroll
            for (int j = 0; j < 4; j++) acc[mt][nt][j] = 0.0f;

    auto issue = [&](int chunk, int stage) {
        const int kt = chunk * GBK;
        const uint32_t sd = sbase + stage * STAGEB;
        CP16(sd + acd0, A + aoff + kt);
        CP16(sd + acd1, A + aoff + kt + 8);
        CP16(sd + ATILEB + bcd, Bhi + boff + kt);
        if (SPLITB)
            CP16(sd + ATILEB + BTILEB + bcd, Blo + boff + kt);
    };

    issue(0, 0); CP_COMMIT();
    issue(1, 1); CP_COMMIT();
    issue(2, 2); CP_COMMIT();

    for (int c = 0; c < NITER; c++) {
        CP_WAIT(2);
        __syncthreads();

        if (c + 3 < NITER) issue(c + 3, (c + 3) & 3);
        CP_COMMIT();

        const uint32_t sb = sbase + (c & 3) * STAGEB;

#pragma unroll
        for (int hk = 0; hk < 2; hk++) {
            const uint32_t oA = hk ? offA1 : offA0;
            const uint32_t oB = hk ? offB1 : offB0;
            uint32_t ah[2][4];
#pragma unroll
            for (int mt = 0; mt < 2; mt++)
                LDSM4(ah[mt], sb + oA + mt * 1024);
#pragma unroll
            for (int np = 0; np < 2; np++) {
                uint32_t bh[4], bl[4];
                LDSM4(bh, sb + ATILEB + oB + np * 1024);
                if (SPLITB)
                    LDSM4(bl, sb + ATILEB + BTILEB + oB + np * 1024);
#pragma unroll
                for (int sub = 0; sub < 2; sub++) {
                    const int nt = np * 2 + sub;
                    const uint32_t b0h = bh[sub * 2], b1h = bh[sub * 2 + 1];
#pragma unroll
                    for (int mt = 0; mt < 2; mt++) {
                        MMA16816(acc[mt][nt], ah[mt], b0h, b1h);
                        if (SPLITB)
                            MMA16816(acc[mt][nt], ah[mt], bl[sub * 2], bl[sub * 2 + 1]);
                    }
                }
            }
        }
        __syncthreads();
    }

    // --- epilogue (R9-proven: direct gmem resid reads) ---
    const int g  = lane >> 2;
    const int tg = lane & 3;
#pragma unroll
    for (int mt = 0; mt < 2; mt++) {
#pragma unroll
        for (int nt = 0; nt < 4; nt++) {
            const int row = blockM + warpM + mt * 16 + g;
            const int col = blockN + warpN + nt * 8 + tg * 2;
            const size_t o0 = (size_t)row * PD + col;
            const size_t o1 = (size_t)(row + 8) * PD + col;
            if (OBF16) {
                *(__nv_bfloat162*)&Cb[o0] = __floats2bfloat162_rn(acc[mt][nt][0], acc[mt][nt][1]);
                *(__nv_bfloat162*)&Cb[o1] = __floats2bfloat162_rn(acc[mt][nt][2], acc[mt][nt][3]);
            } else {
                float2 v0 = make_float2(acc[mt][nt][0], acc[mt][nt][1]);
                float2 v1 = make_float2(acc[mt][nt][2], acc[mt][nt][3]);
                if (EPI) {
                    const float2 bb = *(const float2*)&bias[col];
                    const float2 x0 = *(const float2*)&resid[o0];
                    const float2 x1 = *(const float2*)&resid[o1];
                    v0.x += bb.x + x0.x; v0.y += bb.y + x0.y;
                    v1.x += bb.x + x1.x; v1.y += bb.y + x1.y;
                }
                *(float2*)&Cf[o0] = v0;
                *(float2*)&Cf[o1] = v1;
            }
        }
    }
}

#define GEMM1_SMEM (STAGES * (ATILEB + BTILEB))       // 49152
#define GEMM2_SMEM (STAGES * (ATILEB + 2 * BTILEB))   // 65536

// ---------------------------------------------------------------------------
// Prep: x -> bf16; W_in -> bf16 (hi only); W_out -> (hi, lo) split. One launch.
// ---------------------------------------------------------------------------
#define NX (MT * PD)      // 2097152
#define NW (PD * PD)      // 262144
#define PREP_THREADS ((NX + 2 * NW) / 4)

__device__ __forceinline__ void round4(const float* src, __nv_bfloat16* dst, int i)
{
    const float4 v = *(const float4*)(src + i);
    __align__(8) __nv_bfloat16 h4[4];
    h4[0] = __float2bfloat16(v.x);
    h4[1] = __float2bfloat16(v.y);
    h4[2] = __float2bfloat16(v.z);
    h4[3] = __float2bfloat16(v.w);
    *(uint2*)(dst + i) = *(const uint2*)h4;
}

__device__ __forceinline__ void split4(const float* src, __nv_bfloat16* hi,
                                       __nv_bfloat16* lo, int i)
{
    const float4 v = *(const float4*)(src + i);
    float vv[4] = {v.x, v.y, v.z, v.w};
    __align__(8) __nv_bfloat16 h4[4], l4[4];
#pragma unroll
    for (int j = 0; j < 4; j++) {
        h4[j] = __float2bfloat16(vv[j]);
        l4[j] = __float2bfloat16(vv[j] - __bfloat162float(h4[j]));
    }
    *(uint2*)(hi + i) = *(const uint2*)h4;
    *(uint2*)(lo + i) = *(const uint2*)l4;
}

__global__ __launch_bounds__(256)
void prep_kernel(const float* __restrict__ x,  __nv_bfloat16* __restrict__ xb,
                 const float* __restrict__ Wi, __nv_bfloat16* __restrict__ wih,
                 const float* __restrict__ Wo, __nv_bfloat16* __restrict__ woh, __nv_bfloat16* __restrict__ wol)
{
    const int t = blockIdx.x * blockDim.x + threadIdx.x;
    const int i = t * 4;
    if (i < NX) {
        round4(x, xb, i);
    } else if (i < NX + NW) {
        round4(Wi, wih, i - NX);
    } else {
        split4(Wo, woh, wol, i - NX - NW);
    }
}

// ---------------------------------------------------------------------------
// Fused softmax + gather-fuse (unchanged from R9):
//   w[s,:] = softmax_k(-dist[s, routes[s,k]])  (warp 0 per block)
//   fused[b,s,:] = sum_k w[s,k] * h[b, routes[s,k], :]   (bf16 out)
// ---------------------------------------------------------------------------
__global__ __launch_bounds__(128)
void fuse_kernel(const __nv_bfloat16* __restrict__ h, const int* __restrict__ routes,
                 const float* __restrict__ dist, __nv_bfloat16* __restrict__ f)
{
    const int s   = blockIdx.x;
    const int tid = threadIdx.x;

    __shared__ __align__(8) uint2 wr[PK];   // .x = row*PD*2 (bytes), .y = w bits

    if (tid < 32) {
        const int lane = tid;
        const int r0 = routes[s * PK + lane];
        const int r1 = routes[s * PK + lane + 32];
        const float v0 = -dist[(size_t)s * PS + r0];
        const float v1 = -dist[(size_t)s * PS + r1];

        float m = fmaxf(v0, v1);
#pragma unroll
        for (int off = 16; off > 0; off >>= 1)
            m = fmaxf(m, __shfl_xor_sync(0xFFFFFFFFu, m, off));

        const float e0 = __expf(v0 - m);
        const float e1 = __expf(v1 - m);
        float sum = e0 + e1;
#pragma unroll
        for (int off = 16; off > 0; off >>= 1)
            sum += __shfl_xor_sync(0xFFFFFFFFu, sum, off);
        const float inv = 1.0f / sum;

        wr[lane]      = make_uint2((uint32_t)r0 * (PD * 2), __float_as_uint(e0 * inv));
        wr[lane + 32] = make_uint2((uint32_t)r1 * (PD * 2), __float_as_uint(e1 * inv));
    }
    __syncthreads();

    const int b = tid >> 6;
    const int t = tid & 63;
    const char* hb = (const char*)(h + (size_t)b * PS * PD) + t * 16;

    uint64_t a0 = 0, a1 = 0, a2 = 0, a3 = 0;

#pragma unroll
    for (int k = 0; k < PK; k++) {
        const uint2 e = wr[k];
        const uint4 v = *(const uint4*)(hb + e.x);
        uint64_t wk2;
        asm("mov.b64 %0, {%1, %1};" : "=l"(wk2) : "r"(e.y));
        CVT_FMA2(a0, v.x, wk2);
        CVT_FMA2(a1, v.y, wk2);
        CVT_FMA2(a2, v.z, wk2);
        CVT_FMA2(a3, v.w, wk2);
    }

    float r0, r1, r2, r3, r4, r5, r6, r7;
    asm("mov.b64 {%0, %1}, %2;" : "=f"(r0), "=f"(r1) : "l"(a0));
    asm("mov.b64 {%0, %1}, %2;" : "=f"(r2), "=f"(r3) : "l"(a1));
    asm("mov.b64 {%0, %1}, %2;" : "=f"(r4), "=f"(r5) : "l"(a2));
    asm("mov.b64 {%0, %1}, %2;" : "=f"(r6), "=f"(r7) : "l"(a3));

    __align__(16) __nv_bfloat162 o[4];
    o[0] = __floats2bfloat162_rn(r0, r1);
    o[1] = __floats2bfloat162_rn(r2, r3);
    o[2] = __floats2bfloat162_rn(r4, r5);
    o[3] = __floats2bfloat162_rn(r6, r7);
    *(uint4*)&f[((size_t)b * PS + s) * PD + t * 8] = *(const uint4*)o;
}

// ---------------------------------------------------------------------------
// kernel_launch
// Inputs: 0: x (B,S,D) f32 | 1: routes (S,K) i32 | 2: distances (S,S) f32
//         3: W_in (D,D) f32 | 4: W_out (D,D) f32 | 5: b_out (D,) f32
// ---------------------------------------------------------------------------
extern "C" void kernel_launch(void* const* d_in, const int* in_sizes, int n_in,
                              void* d_out, int out_size)
{
    const float* x      = (const float*)d_in[0];
    const int*   routes = (const int*)  d_in[1];
    const float* dist   = (const float*)d_in[2];
    const float* W_in   = (const float*)d_in[3];
    const float* W_out  = (const float*)d_in[4];
    const float* b_out  = (const float*)d_in[5];
    float*       out    = (float*)d_out;

    __nv_bfloat16 *xb, *hb, *fb, *wih, *woh, *wol;
    cudaGetSymbolAddress((void**)&xb,  g_x_bf);
    cudaGetSymbolAddress((void**)&hb,  g_h_bf);
    cudaGetSymbolAddress((void**)&fb,  g_f_bf);
    cudaGetSymbolAddress((void**)&wih, g_wi_hi);
    cudaGetSymbolAddress((void**)&woh, g_wo_hi);
    cudaGetSymbolAddress((void**)&wol, g_wo_lo);

    static bool attr_set = false;
    if (!attr_set) {
        cudaFuncSetAttribute((const void*)mma_gemm_kernel<false, true, false>,
                             cudaFuncAttributeMaxDynamicSharedMemorySize, GEMM1_SMEM);
        cudaFuncSetAttribute((const void*)mma_gemm_kernel<true, false, true>,
                             cudaFuncAttributeMaxDynamicSharedMemorySize, GEMM2_SMEM);
        attr_set = true;
    }

    // 0) prep: x->bf16, W_in->bf16, W_out split
    prep_kernel<<<PREP_THREADS / 256, 256>>>(x, xb, W_in, wih, W_out, woh, wol);

    // 1) h = x @ W_in^T  (bf16 out; single-term B)
    {
        dim3 grid(PD / GBN, MT / GBM);   // 8 x 32 = 256 CTAs, 2/SM
        mma_gemm_kernel<false, true, false><<<grid, 256, GEMM1_SMEM>>>(
            xb, wih, nullptr, nullptr, hb, nullptr, nullptr);
    }

    // 2) softmax + gather-fuse -> bf16 fused (one kernel)
    fuse_kernel<<<PS, 128>>>(hb, routes, dist, fb);

    // 3) out = fused @ W_out^T + b_out + x  (split B)
    {
        dim3 grid(PD / GBN, MT / GBM);
        mma_gemm_kernel<true, false, true><<<grid, 256, GEMM2_SMEM>>>(
            fb, woh, wol, out, nullptr, b_out, x);
    }
}

// round 12
// speedup vs baseline: 1.1291x; 1.0061x over previous
#include <cuda_runtime.h>
#include <cuda_bf16.h>
#include <cstdint>

// Problem constants (B=2, S=2048, D=512, K=64)
#define PB 2
#define PS 2048
#define PD 512
#define PK 64
#define MT (PB * PS)   // 4096 rows total

// ---------------------------------------------------------------------------
// Scratch (device globals — no allocation allowed)
// ---------------------------------------------------------------------------
__device__ __align__(16) __nv_bfloat16 g_x_bf[MT * PD];    // bf16(x)
__device__ __align__(16) __nv_bfloat16 g_h_bf[MT * PD];    // bf16(h)
__device__ __align__(16) __nv_bfloat16 g_f_bf[MT * PD];    // bf16(fused)
__device__ __align__(16) __nv_bfloat16 g_wi_hi[PD * PD];
__device__ __align__(16) __nv_bfloat16 g_wo_hi[PD * PD];
__device__ __align__(16) __nv_bfloat16 g_wo_lo[PD * PD];

// ---------------------------------------------------------------------------
// PTX helpers (sm_80/sm_100-level only — harness compiles via compute_103 PTX,
// which rejects 'a'-gated tcgen05/TMEM; f32x2 packed math is plain sm_100+)
// ---------------------------------------------------------------------------
__device__ __forceinline__ uint32_t smem_u32(const void* p) {
    uint32_t a;
    asm("{ .reg .u64 t; cvta.to.shared.u64 t, %1; cvt.u32.u64 %0, t; }" : "=r"(a) : "l"(p));
    return a;
}

#define LDSM4(r, addr) \
    asm volatile("ldmatrix.sync.aligned.m8n8.x4.shared.b16 {%0,%1,%2,%3}, [%4];" \
                 : "=r"((r)[0]), "=r"((r)[1]), "=r"((r)[2]), "=r"((r)[3]) : "r"(addr))

#define MMA16816(d, a, b0, b1) \
    asm volatile("mma.sync.aligned.m16n8k16.row.col.f32.bf16.bf16.f32 " \
                 "{%0,%1,%2,%3}, {%4,%5,%6,%7}, {%8,%9}, {%0,%1,%2,%3};" \
                 : "+f"((d)[0]), "+f"((d)[1]), "+f"((d)[2]), "+f"((d)[3]) \
                 : "r"((a)[0]), "r"((a)[1]), "r"((a)[2]), "r"((a)[3]), "r"(b0), "r"(b1))

#define CP16(dst, src) \
    asm volatile("cp.async.cg.shared.global [%0], [%1], 16;" :: "r"(dst), "l"(src))
#define CP_COMMIT()  asm volatile("cp.async.commit_group;" ::: "memory")
#define CP_WAIT(N)   asm volatile("cp.async.wait_group %0;" :: "n"(N) : "memory")

// Packed bf16x2-word -> f32x2 convert + packed FMA:  acc(f32x2) += wk2 * {lo,hi}
#define CVT_FMA2(acc, u, wk2) \
    asm("{\n\t" \
        ".reg .b32 lo, hi;\n\t" \
        ".reg .b64 val;\n\t" \
        "shl.b32 lo, %1, 16;\n\t" \
        "and.b32 hi, %1, 0xFFFF0000;\n\t" \
        "mov.b64 val, {lo, hi};\n\t" \
        "fma.rn.f32x2 %0, %2, val, %0;\n\t" \
        "}" : "+l"(acc) : "r"(u), "l"(wk2))

// ---------------------------------------------------------------------------
// GEMM (NT): C[m,n] = sum_k A[m,k]*B[n,k]
//   A: plain bf16.  SPLITB: B ~ Bhi + Blo (2 MMA terms); else B = Bhi only.
// Tile 128x64, BK=32, 8 warps (4m x 2n), 4-stage cp.async ring, 2 CTAs/SM.
// SPLITB mainloop: hi-term MMAs for all (sub,mt) first, then lo-term MMAs —
// accumulator RAW distance 4 instead of 1 (HMMA latency cover).
// smem row = 64B; swizzle u' = u ^ ((row>>1)&3)
// ---------------------------------------------------------------------------
#define GBM 128
#define GBN 64
#define GBK 32
#define NITER (PD / GBK)       // 16
#define STAGES 4
#define ATILEB (128 * 64)      // 8192 B
#define BTILEB (64 * 64)       // 4096 B

__device__ __forceinline__ uint32_t swz(int row, int u) {
    return (uint32_t)(row * 64 + ((u ^ ((row >> 1) & 3)) * 16));
}

// OBF16: write C as bf16 to Cb (no epilogue). Else fp32 to Cf with bias+resid if EPI.
template <bool EPI, bool OBF16, bool SPLITB>
__global__ __launch_bounds__(256, 2)
void mma_gemm_kernel(const __nv_bfloat16* __restrict__ A,
                     const __nv_bfloat16* __restrict__ Bhi, const __nv_bfloat16* __restrict__ Blo,
                     float* __restrict__ Cf, __nv_bfloat16* __restrict__ Cb,
                     const float* __restrict__ bias, const float* __restrict__ resid)
{
    constexpr int STAGEB = ATILEB + (SPLITB ? 2 : 1) * BTILEB;

    extern __shared__ __align__(128) char sm[];
    const uint32_t sbase = smem_u32(sm);

    const int tid  = threadIdx.x;
    const int lane = tid & 31;
    const int wid  = tid >> 5;
    const int warpM = (wid & 3) * 32;
    const int warpN = (wid >> 2) * 32;
    const int blockM = blockIdx.y * GBM;
    const int blockN = blockIdx.x * GBN;

    // cp.async mapping
    const int arow = tid >> 1;
    const int au   = (tid & 1) * 2;
    const uint32_t acd0 = swz(arow, au);
    const uint32_t acd1 = swz(arow, au + 1);
    const size_t aoff = (size_t)(blockM + arow) * PD + au * 8;
    const int brow = tid >> 2;
    const int bu   = tid & 3;
    const uint32_t bcd = swz(brow, bu);
    const size_t boff = (size_t)(blockN + brow) * PD + bu * 8;

    // ldmatrix lane mapping (fragment layout identical to proven R4-R11 kernels)
    const int mx = lane >> 3;
    const int lr = lane & 7;
    const int rA = (mx & 1) * 8 + lr;
    const int uA = mx >> 1;
    const int rB = (mx >> 1) * 8 + lr;
    const int uB = mx & 1;
    const uint32_t offA0 = (uint32_t)(warpM + rA) * 64 + ((0 + uA) ^ ((rA >> 1) & 3)) * 16;
    const uint32_t offA1 = (uint32_t)(warpM + rA) * 64 + ((2 + uA) ^ ((rA >> 1) & 3)) * 16;
    const uint32_t offB0 = (uint32_t)(warpN + rB) * 64 + ((0 + uB) ^ ((rB >> 1) & 3)) * 16;
    const uint32_t offB1 = (uint32_t)(warpN + rB) * 64 + ((2 + uB) ^ ((rB >> 1) & 3)) * 16;

    float acc[2][4][4];
#pragma unroll
    for (int mt = 0; mt < 2; mt++)
#pragma unroll
        for (int nt = 0; nt < 4; nt++)
#pragma unroll
            for (int j = 0; j < 4; j++) acc[mt][nt][j] = 0.0f;

    auto issue = [&](int chunk, int stage) {
        const int kt = chunk * GBK;
        const uint32_t sd = sbase + stage * STAGEB;
        CP16(sd + acd0, A + aoff + kt);
        CP16(sd + acd1, A + aoff + kt + 8);
        CP16(sd + ATILEB + bcd, Bhi + boff + kt);
        if (SPLITB)
            CP16(sd + ATILEB + BTILEB + bcd, Blo + boff + kt);
    };

    issue(0, 0); CP_COMMIT();
    issue(1, 1); CP_COMMIT();
    issue(2, 2); CP_COMMIT();

    for (int c = 0; c < NITER; c++) {
        CP_WAIT(2);
        __syncthreads();

        if (c + 3 < NITER) issue(c + 3, (c + 3) & 3);
        CP_COMMIT();

        const uint32_t sb = sbase + (c & 3) * STAGEB;

#pragma unroll
        for (int hk = 0; hk < 2; hk++) {
            const uint32_t oA = hk ? offA1 : offA0;
            const uint32_t oB = hk ? offB1 : offB0;
            uint32_t ah[2][4];
#pragma unroll
            for (int mt = 0; mt < 2; mt++)
                LDSM4(ah[mt], sb + oA + mt * 1024);
#pragma unroll
            for (int np = 0; np < 2; np++) {
                uint32_t bh[4], bl[4];
                LDSM4(bh, sb + ATILEB + oB + np * 1024);
                if (SPLITB)
                    LDSM4(bl, sb + ATILEB + BTILEB + oB + np * 1024);
                // hi-term MMAs: 4 distinct accumulators
#pragma unroll
                for (int sub = 0; sub < 2; sub++) {
                    const int nt = np * 2 + sub;
#pragma unroll
                    for (int mt = 0; mt < 2; mt++)
                        MMA16816(acc[mt][nt], ah[mt], bh[sub * 2], bh[sub * 2 + 1]);
                }
                // lo-term MMAs: same accs, RAW distance 4
                if (SPLITB) {
#pragma unroll
                    for (int sub = 0; sub < 2; sub++) {
                        const int nt = np * 2 + sub;
#pragma unroll
                        for (int mt = 0; mt < 2; mt++)
                            MMA16816(acc[mt][nt], ah[mt], bl[sub * 2], bl[sub * 2 + 1]);
                    }
                }
            }
        }
        __syncthreads();
    }

    // --- epilogue (direct gmem resid reads) ---
    const int g  = lane >> 2;
    const int tg = lane & 3;
#pragma unroll
    for (int mt = 0; mt < 2; mt++) {
#pragma unroll
        for (int nt = 0; nt < 4; nt++) {
            const int row = blockM + warpM + mt * 16 + g;
            const int col = blockN + warpN + nt * 8 + tg * 2;
            const size_t o0 = (size_t)row * PD + col;
            const size_t o1 = (size_t)(row + 8) * PD + col;
            if (OBF16) {
                *(__nv_bfloat162*)&Cb[o0] = __floats2bfloat162_rn(acc[mt][nt][0], acc[mt][nt][1]);
                *(__nv_bfloat162*)&Cb[o1] = __floats2bfloat162_rn(acc[mt][nt][2], acc[mt][nt][3]);
            } else {
                float2 v0 = make_float2(acc[mt][nt][0], acc[mt][nt][1]);
                float2 v1 = make_float2(acc[mt][nt][2], acc[mt][nt][3]);
                if (EPI) {
                    const float2 bb = *(const float2*)&bias[col];
                    const float2 x0 = *(const float2*)&resid[o0];
                    const float2 x1 = *(const float2*)&resid[o1];
                    v0.x += bb.x + x0.x; v0.y += bb.y + x0.y;
                    v1.x += bb.x + x1.x; v1.y += bb.y + x1.y;
                }
                *(float2*)&Cf[o0] = v0;
                *(float2*)&Cf[o1] = v1;
            }
        }
    }
}

#define GEMM1_SMEM (STAGES * (ATILEB + BTILEB))       // 49152
#define GEMM2_SMEM (STAGES * (ATILEB + 2 * BTILEB))   // 65536

// ---------------------------------------------------------------------------
// Prep: x -> bf16; W_in -> bf16 (hi only); W_out -> (hi, lo) split. One launch.
// ---------------------------------------------------------------------------
#define NX (MT * PD)      // 2097152
#define NW (PD * PD)      // 262144
#define PREP_THREADS ((NX + 2 * NW) / 4)

__device__ __forceinline__ void round4(const float* src, __nv_bfloat16* dst, int i)
{
    const float4 v = *(const float4*)(src + i);
    __align__(8) __nv_bfloat16 h4[4];
    h4[0] = __float2bfloat16(v.x);
    h4[1] = __float2bfloat16(v.y);
    h4[2] = __float2bfloat16(v.z);
    h4[3] = __float2bfloat16(v.w);
    *(uint2*)(dst + i) = *(const uint2*)h4;
}

__device__ __forceinline__ void split4(const float* src, __nv_bfloat16* hi,
                                       __nv_bfloat16* lo, int i)
{
    const float4 v = *(const float4*)(src + i);
    float vv[4] = {v.x, v.y, v.z, v.w};
    __align__(8) __nv_bfloat16 h4[4], l4[4];
#pragma unroll
    for (int j = 0; j < 4; j++) {
        h4[j] = __float2bfloat16(vv[j]);
        l4[j] = __float2bfloat16(vv[j] - __bfloat162float(h4[j]));
    }
    *(uint2*)(hi + i) = *(const uint2*)h4;
    *(uint2*)(lo + i) = *(const uint2*)l4;
}

__global__ __launch_bounds__(256)
void prep_kernel(const float* __restrict__ x,  __nv_bfloat16* __restrict__ xb,
                 const float* __restrict__ Wi, __nv_bfloat16* __restrict__ wih,
                 const float* __restrict__ Wo, __nv_bfloat16* __restrict__ woh, __nv_bfloat16* __restrict__ wol)
{
    const int t = blockIdx.x * blockDim.x + threadIdx.x;
    const int i = t * 4;
    if (i < NX) {
        round4(x, xb, i);
    } else if (i < NX + NW) {
        round4(Wi, wih, i - NX);
    } else {
        split4(Wo, woh, wol, i - NX - NW);
    }
}

// ---------------------------------------------------------------------------
// Fused softmax + gather-fuse (proven R9 version):
//   w[s,:] = softmax_k(-dist[s, routes[s,k]])  (warp 0 per block)
//   fused[b,s,:] = sum_k w[s,k] * h[b, routes[s,k], :]   (bf16 out)
// ---------------------------------------------------------------------------
__global__ __launch_bounds__(128)
void fuse_kernel(const __nv_bfloat16* __restrict__ h, const int* __restrict__ routes,
                 const float* __restrict__ dist, __nv_bfloat16* __restrict__ f)
{
    const int s   = blockIdx.x;
    const int tid = threadIdx.x;

    __shared__ __align__(8) uint2 wr[PK];   // .x = row*PD*2 (bytes), .y = w bits

    if (tid < 32) {
        const int lane = tid;
        const int r0 = routes[s * PK + lane];
        const int r1 = routes[s * PK + lane + 32];
        const float v0 = -dist[(size_t)s * PS + r0];
        const float v1 = -dist[(size_t)s * PS + r1];

        float m = fmaxf(v0, v1);
#pragma unroll
        for (int off = 16; off > 0; off >>= 1)
            m = fmaxf(m, __shfl_xor_sync(0xFFFFFFFFu, m, off));

        const float e0 = __expf(v0 - m);
        const float e1 = __expf(v1 - m);
        float sum = e0 + e1;
#pragma unroll
        for (int off = 16; off > 0; off >>= 1)
            sum += __shfl_xor_sync(0xFFFFFFFFu, sum, off);
        const float inv = 1.0f / sum;

        wr[lane]      = make_uint2((uint32_t)r0 * (PD * 2), __float_as_uint(e0 * inv));
        wr[lane + 32] = make_uint2((uint32_t)r1 * (PD * 2), __float_as_uint(e1 * inv));
    }
    __syncthreads();

    const int b = tid >> 6;
    const int t = tid & 63;
    const char* hb = (const char*)(h + (size_t)b * PS * PD) + t * 16;

    uint64_t a0 = 0, a1 = 0, a2 = 0, a3 = 0;

#pragma unroll
    for (int k = 0; k < PK; k++) {
        const uint2 e = wr[k];
        const uint4 v = *(const uint4*)(hb + e.x);
        uint64_t wk2;
        asm("mov.b64 %0, {%1, %1};" : "=l"(wk2) : "r"(e.y));
        CVT_FMA2(a0, v.x, wk2);
        CVT_FMA2(a1, v.y, wk2);
        CVT_FMA2(a2, v.z, wk2);
        CVT_FMA2(a3, v.w, wk2);
    }

    float r0, r1, r2, r3, r4, r5, r6, r7;
    asm("mov.b64 {%0, %1}, %2;" : "=f"(r0), "=f"(r1) : "l"(a0));
    asm("mov.b64 {%0, %1}, %2;" : "=f"(r2), "=f"(r3) : "l"(a1));
    asm("mov.b64 {%0, %1}, %2;" : "=f"(r4), "=f"(r5) : "l"(a2));
    asm("mov.b64 {%0, %1}, %2;" : "=f"(r6), "=f"(r7) : "l"(a3));

    __align__(16) __nv_bfloat162 o[4];
    o[0] = __floats2bfloat162_rn(r0, r1);
    o[1] = __floats2bfloat162_rn(r2, r3);
    o[2] = __floats2bfloat162_rn(r4, r5);
    o[3] = __floats2bfloat162_rn(r6, r7);
    *(uint4*)&f[((size_t)b * PS + s) * PD + t * 8] = *(const uint4*)o;
}

// ---------------------------------------------------------------------------
// kernel_launch
// Inputs: 0: x (B,S,D) f32 | 1: routes (S,K) i32 | 2: distances (S,S) f32
//         3: W_in (D,D) f32 | 4: W_out (D,D) f32 | 5: b_out (D,) f32
// ---------------------------------------------------------------------------
extern "C" void kernel_launch(void* const* d_in, const int* in_sizes, int n_in,
                              void* d_out, int out_size)
{
    const float* x      = (const float*)d_in[0];
    const int*   routes = (const int*)  d_in[1];
    const float* dist   = (const float*)d_in[2];
    const float* W_in   = (const float*)d_in[3];
    const float* W_out  = (const float*)d_in[4];
    const float* b_out  = (const float*)d_in[5];
    float*       out    = (float*)d_out;

    __nv_bfloat16 *xb, *hb, *fb, *wih, *woh, *wol;
    cudaGetSymbolAddress((void**)&xb,  g_x_bf);
    cudaGetSymbolAddress((void**)&hb,  g_h_bf);
    cudaGetSymbolAddress((void**)&fb,  g_f_bf);
    cudaGetSymbolAddress((void**)&wih, g_wi_hi);
    cudaGetSymbolAddress((void**)&woh, g_wo_hi);
    cudaGetSymbolAddress((void**)&wol, g_wo_lo);

    static bool attr_set = false;
    if (!attr_set) {
        cudaFuncSetAttribute((const void*)mma_gemm_kernel<false, true, false>,
                             cudaFuncAttributeMaxDynamicSharedMemorySize, GEMM1_SMEM);
        cudaFuncSetAttribute((const void*)mma_gemm_kernel<true, false, true>,
                             cudaFuncAttributeMaxDynamicSharedMemorySize, GEMM2_SMEM);
        attr_set = true;
    }

    // 0) prep: x->bf16, W_in->bf16, W_out split
    prep_kernel<<<PREP_THREADS / 256, 256>>>(x, xb, W_in, wih, W_out, woh, wol);

    // 1) h = x @ W_in^T  (bf16 out; single-term B)
    {
        dim3 grid(PD / GBN, MT / GBM);   // 8 x 32 = 256 CTAs, 2/SM
        mma_gemm_kernel<false, true, false><<<grid, 256, GEMM1_SMEM>>>(
            xb, wih, nullptr, nullptr, hb, nullptr, nullptr);
    }

    // 2) softmax + gather-fuse -> bf16 fused (one kernel)
    fuse_kernel<<<PS, 128>>>(hb, routes, dist, fb);

    // 3) out = fused @ W_out^T + b_out + x  (split B)
    {
        dim3 grid(PD / GBN, MT / GBM);
        mma_gemm_kernel<true, false, true><<<grid, 256, GEMM2_SMEM>>>(
            fb, woh, wol, out, nullptr, b_out, x);
    }
}

// round 13
// speedup vs baseline: 1.2291x; 1.0886x over previous
#include <cuda_runtime.h>
#include <cuda_bf16.h>
#include <cstdint>

// Problem constants (B=2, S=2048, D=512, K=64)
#define PB 2
#define PS 2048
#define PD 512
#define PK 64
#define MT (PB * PS)   // 4096 rows total

// ---------------------------------------------------------------------------
// Scratch (device globals — no allocation allowed)
// ---------------------------------------------------------------------------
__device__ __align__(16) __nv_bfloat16 g_x_bf[MT * PD];    // bf16(x)
__device__ __align__(16) __nv_bfloat16 g_h_bf[MT * PD];    // bf16(h)
__device__ __align__(16) __nv_bfloat16 g_f_bf[MT * PD];    // bf16(fused)
__device__ __align__(16) __nv_bfloat16 g_wi_bf[PD * PD];
__device__ __align__(16) __nv_bfloat16 g_wo_bf[PD * PD];

// ---------------------------------------------------------------------------
// PTX helpers (sm_80/sm_100-level only — harness compiles via compute_103 PTX,
// which rejects 'a'-gated tcgen05/TMEM; f32x2 packed math is plain sm_100+)
// ---------------------------------------------------------------------------
__device__ __forceinline__ uint32_t smem_u32(const void* p) {
    uint32_t a;
    asm("{ .reg .u64 t; cvta.to.shared.u64 t, %1; cvt.u32.u64 %0, t; }" : "=r"(a) : "l"(p));
    return a;
}

#define LDSM4(r, addr) \
    asm volatile("ldmatrix.sync.aligned.m8n8.x4.shared.b16 {%0,%1,%2,%3}, [%4];" \
                 : "=r"((r)[0]), "=r"((r)[1]), "=r"((r)[2]), "=r"((r)[3]) : "r"(addr))

#define MMA16816(d, a, b0, b1) \
    asm volatile("mma.sync.aligned.m16n8k16.row.col.f32.bf16.bf16.f32 " \
                 "{%0,%1,%2,%3}, {%4,%5,%6,%7}, {%8,%9}, {%0,%1,%2,%3};" \
                 : "+f"((d)[0]), "+f"((d)[1]), "+f"((d)[2]), "+f"((d)[3]) \
                 : "r"((a)[0]), "r"((a)[1]), "r"((a)[2]), "r"((a)[3]), "r"(b0), "r"(b1))

#define CP16(dst, src) \
    asm volatile("cp.async.cg.shared.global [%0], [%1], 16;" :: "r"(dst), "l"(src))
#define CP_COMMIT()  asm volatile("cp.async.commit_group;" ::: "memory")
#define CP_WAIT(N)   asm volatile("cp.async.wait_group %0;" :: "n"(N) : "memory")

// Packed bf16x2-word -> f32x2 convert + packed FMA:  acc(f32x2) += wk2 * {lo,hi}
#define CVT_FMA2(acc, u, wk2) \
    asm("{\n\t" \
        ".reg .b32 lo, hi;\n\t" \
        ".reg .b64 val;\n\t" \
        "shl.b32 lo, %1, 16;\n\t" \
        "and.b32 hi, %1, 0xFFFF0000;\n\t" \
        "mov.b64 val, {lo, hi};\n\t" \
        "fma.rn.f32x2 %0, %2, val, %0;\n\t" \
        "}" : "+l"(acc) : "r"(u), "l"(wk2))

// ---------------------------------------------------------------------------
// GEMM (NT): C[m,n] = sum_k A[m,k]*B[n,k]   (all operands plain bf16, fp32 acc)
// Tile 128x64, BK=32, 8 warps (4m x 2n), 4-stage cp.async ring, 2 CTAs/SM.
// Proven R9/R11 interleaved LDSM/MMA mainloop, single-term B.
// smem row = 64B; swizzle u' = u ^ ((row>>1)&3)
// ---------------------------------------------------------------------------
#define GBM 128
#define GBN 64
#define GBK 32
#define NITER (PD / GBK)       // 16
#define STAGES 4
#define ATILEB (128 * 64)      // 8192 B
#define BTILEB (64 * 64)       // 4096 B
#define STAGEB (ATILEB + BTILEB)        // 12288 B
#define GEMM_SMEM (STAGES * STAGEB)     // 49152 B

__device__ __forceinline__ uint32_t swz(int row, int u) {
    return (uint32_t)(row * 64 + ((u ^ ((row >> 1) & 3)) * 16));
}

// OBF16: write C as bf16 to Cb (no epilogue). Else fp32 to Cf with bias+resid if EPI.
template <bool EPI, bool OBF16>
__global__ __launch_bounds__(256, 2)
void mma_gemm_kernel(const __nv_bfloat16* __restrict__ A,
                     const __nv_bfloat16* __restrict__ B,
                     float* __restrict__ Cf, __nv_bfloat16* __restrict__ Cb,
                     const float* __restrict__ bias, const float* __restrict__ resid)
{
    extern __shared__ __align__(128) char sm[];
    const uint32_t sbase = smem_u32(sm);

    const int tid  = threadIdx.x;
    const int lane = tid & 31;
    const int wid  = tid >> 5;
    const int warpM = (wid & 3) * 32;
    const int warpN = (wid >> 2) * 32;
    const int blockM = blockIdx.y * GBM;
    const int blockN = blockIdx.x * GBN;

    // cp.async mapping
    const int arow = tid >> 1;
    const int au   = (tid & 1) * 2;
    const uint32_t acd0 = swz(arow, au);
    const uint32_t acd1 = swz(arow, au + 1);
    const size_t aoff = (size_t)(blockM + arow) * PD + au * 8;
    const int brow = tid >> 2;
    const int bu   = tid & 3;
    const uint32_t bcd = swz(brow, bu);
    const size_t boff = (size_t)(blockN + brow) * PD + bu * 8;

    // ldmatrix lane mapping (fragment layout identical to proven R4-R12 kernels)
    const int mx = lane >> 3;
    const int lr = lane & 7;
    const int rA = (mx & 1) * 8 + lr;
    const int uA = mx >> 1;
    const int rB = (mx >> 1) * 8 + lr;
    const int uB = mx & 1;
    const uint32_t offA0 = (uint32_t)(warpM + rA) * 64 + ((0 + uA) ^ ((rA >> 1) & 3)) * 16;
    const uint32_t offA1 = (uint32_t)(warpM + rA) * 64 + ((2 + uA) ^ ((rA >> 1) & 3)) * 16;
    const uint32_t offB0 = (uint32_t)(warpN + rB) * 64 + ((0 + uB) ^ ((rB >> 1) & 3)) * 16;
    const uint32_t offB1 = (uint32_t)(warpN + rB) * 64 + ((2 + uB) ^ ((rB >> 1) & 3)) * 16;

    float acc[2][4][4];
#pragma unroll
    for (int mt = 0; mt < 2; mt++)
#pragma unroll
        for (int nt = 0; nt < 4; nt++)
#pragma unroll
            for (int j = 0; j < 4; j++) acc[mt][nt][j] = 0.0f;

    auto issue = [&](int chunk, int stage) {
        const int kt = chunk * GBK;
        const uint32_t sd = sbase + stage * STAGEB;
        CP16(sd + acd0, A + aoff + kt);
        CP16(sd + acd1, A + aoff + kt + 8);
        CP16(sd + ATILEB + bcd, B + boff + kt);
    };

    issue(0, 0); CP_COMMIT();
    issue(1, 1); CP_COMMIT();
    issue(2, 2); CP_COMMIT();

    for (int c = 0; c < NITER; c++) {
        CP_WAIT(2);
        __syncthreads();

        if (c + 3 < NITER) issue(c + 3, (c + 3) & 3);
        CP_COMMIT();

        const uint32_t sb = sbase + (c & 3) * STAGEB;

#pragma unroll
        for (int hk = 0; hk < 2; hk++) {
            const uint32_t oA = hk ? offA1 : offA0;
            const uint32_t oB = hk ? offB1 : offB0;
            uint32_t ah[2][4];
#pragma unroll
            for (int mt = 0; mt < 2; mt++)
                LDSM4(ah[mt], sb + oA + mt * 1024);
#pragma unroll
            for (int np = 0; np < 2; np++) {
                uint32_t bh[4];
                LDSM4(bh, sb + ATILEB + oB + np * 1024);
#pragma unroll
                for (int sub = 0; sub < 2; sub++) {
                    const int nt = np * 2 + sub;
#pragma unroll
                    for (int mt = 0; mt < 2; mt++)
                        MMA16816(acc[mt][nt], ah[mt], bh[sub * 2], bh[sub * 2 + 1]);
                }
            }
        }
        __syncthreads();
    }

    // --- epilogue (direct gmem resid reads) ---
    const int g  = lane >> 2;
    const int tg = lane & 3;
#pragma unroll
    for (int mt = 0; mt < 2; mt++) {
#pragma unroll
        for (int nt = 0; nt < 4; nt++) {
            const int row = blockM + warpM + mt * 16 + g;
            const int col = blockN + warpN + nt * 8 + tg * 2;
            const size_t o0 = (size_t)row * PD + col;
            const size_t o1 = (size_t)(row + 8) * PD + col;
            if (OBF16) {
                *(__nv_bfloat162*)&Cb[o0] = __floats2bfloat162_rn(acc[mt][nt][0], acc[mt][nt][1]);
                *(__nv_bfloat162*)&Cb[o1] = __floats2bfloat162_rn(acc[mt][nt][2], acc[mt][nt][3]);
            } else {
                float2 v0 = make_float2(acc[mt][nt][0], acc[mt][nt][1]);
                float2 v1 = make_float2(acc[mt][nt][2], acc[mt][nt][3]);
                if (EPI) {
                    const float2 bb = *(const float2*)&bias[col];
                    const float2 x0 = *(const float2*)&resid[o0];
                    const float2 x1 = *(const float2*)&resid[o1];
                    v0.x += bb.x + x0.x; v0.y += bb.y + x0.y;
                    v1.x += bb.x + x1.x; v1.y += bb.y + x1.y;
                }
                *(float2*)&Cf[o0] = v0;
                *(float2*)&Cf[o1] = v1;
            }
        }
    }
}

// ---------------------------------------------------------------------------
// Prep: x, W_in, W_out -> bf16. One launch.
// ---------------------------------------------------------------------------
#define NX (MT * PD)      // 2097152
#define NW (PD * PD)      // 262144
#define PREP_THREADS ((NX + 2 * NW) / 4)

__device__ __forceinline__ void round4(const float* src, __nv_bfloat16* dst, int i)
{
    const float4 v = *(const float4*)(src + i);
    __align__(8) __nv_bfloat16 h4[4];
    h4[0] = __float2bfloat16(v.x);
    h4[1] = __float2bfloat16(v.y);
    h4[2] = __float2bfloat16(v.z);
    h4[3] = __float2bfloat16(v.w);
    *(uint2*)(dst + i) = *(const uint2*)h4;
}

__global__ __launch_bounds__(256)
void prep_kernel(const float* __restrict__ x,  __nv_bfloat16* __restrict__ xb,
                 const float* __restrict__ Wi, __nv_bfloat16* __restrict__ wib,
                 const float* __restrict__ Wo, __nv_bfloat16* __restrict__ wob)
{
    const int t = blockIdx.x * blockDim.x + threadIdx.x;
    const int i = t * 4;
    if (i < NX) {
        round4(x, xb, i);
    } else if (i < NX + NW) {
        round4(Wi, wib, i - NX);
    } else {
        round4(Wo, wob, i - NX - NW);
    }
}

// ---------------------------------------------------------------------------
// Fused softmax + gather-fuse (proven R9 version):
//   w[s,:] = softmax_k(-dist[s, routes[s,k]])  (warp 0 per block)
//   fused[b,s,:] = sum_k w[s,k] * h[b, routes[s,k], :]   (bf16 out)
// ---------------------------------------------------------------------------
__global__ __launch_bounds__(128)
void fuse_kernel(const __nv_bfloat16* __restrict__ h, const int* __restrict__ routes,
                 const float* __restrict__ dist, __nv_bfloat16* __restrict__ f)
{
    const int s   = blockIdx.x;
    const int tid = threadIdx.x;

    __shared__ __align__(8) uint2 wr[PK];   // .x = row*PD*2 (bytes), .y = w bits

    if (tid < 32) {
        const int lane = tid;
        const int r0 = routes[s * PK + lane];
        const int r1 = routes[s * PK + lane + 32];
        const float v0 = -dist[(size_t)s * PS + r0];
        const float v1 = -dist[(size_t)s * PS + r1];

        float m = fmaxf(v0, v1);
#pragma unroll
        for (int off = 16; off > 0; off >>= 1)
            m = fmaxf(m, __shfl_xor_sync(0xFFFFFFFFu, m, off));

        const float e0 = __expf(v0 - m);
        const float e1 = __expf(v1 - m);
        float sum = e0 + e1;
#pragma unroll
        for (int off = 16; off > 0; off >>= 1)
            sum += __shfl_xor_sync(0xFFFFFFFFu, sum, off);
        const float inv = 1.0f / sum;

        wr[lane]      = make_uint2((uint32_t)r0 * (PD * 2), __float_as_uint(e0 * inv));
        wr[lane + 32] = make_uint2((uint32_t)r1 * (PD * 2), __float_as_uint(e1 * inv));
    }
    __syncthreads();

    const int b = tid >> 6;
    const int t = tid & 63;
    const char* hb = (const char*)(h + (size_t)b * PS * PD) + t * 16;

    uint64_t a0 = 0, a1 = 0, a2 = 0, a3 = 0;

#pragma unroll
    for (int k = 0; k < PK; k++) {
        const uint2 e = wr[k];
        const uint4 v = *(const uint4*)(hb + e.x);
        uint64_t wk2;
        asm("mov.b64 %0, {%1, %1};" : "=l"(wk2) : "r"(e.y));
        CVT_FMA2(a0, v.x, wk2);
        CVT_FMA2(a1, v.y, wk2);
        CVT_FMA2(a2, v.z, wk2);
        CVT_FMA2(a3, v.w, wk2);
    }

    float r0, r1, r2, r3, r4, r5, r6, r7;
    asm("mov.b64 {%0, %1}, %2;" : "=f"(r0), "=f"(r1) : "l"(a0));
    asm("mov.b64 {%0, %1}, %2;" : "=f"(r2), "=f"(r3) : "l"(a1));
    asm("mov.b64 {%0, %1}, %2;" : "=f"(r4), "=f"(r5) : "l"(a2));
    asm("mov.b64 {%0, %1}, %2;" : "=f"(r6), "=f"(r7) : "l"(a3));

    __align__(16) __nv_bfloat162 o[4];
    o[0] = __floats2bfloat162_rn(r0, r1);
    o[1] = __floats2bfloat162_rn(r2, r3);
    o[2] = __floats2bfloat162_rn(r4, r5);
    o[3] = __floats2bfloat162_rn(r6, r7);
    *(uint4*)&f[((size_t)b * PS + s) * PD + t * 8] = *(const uint4*)o;
}

// ---------------------------------------------------------------------------
// kernel_launch
// Inputs: 0: x (B,S,D) f32 | 1: routes (S,K) i32 | 2: distances (S,S) f32
//         3: W_in (D,D) f32 | 4: W_out (D,D) f32 | 5: b_out (D,) f32
// ---------------------------------------------------------------------------
extern "C" void kernel_launch(void* const* d_in, const int* in_sizes, int n_in,
                              void* d_out, int out_size)
{
    const float* x      = (const float*)d_in[0];
    const int*   routes = (const int*)  d_in[1];
    const float* dist   = (const float*)d_in[2];
    const float* W_in   = (const float*)d_in[3];
    const float* W_out  = (const float*)d_in[4];
    const float* b_out  = (const float*)d_in[5];
    float*       out    = (float*)d_out;

    __nv_bfloat16 *xb, *hb, *fb, *wib, *wob;
    cudaGetSymbolAddress((void**)&xb,  g_x_bf);
    cudaGetSymbolAddress((void**)&hb,  g_h_bf);
    cudaGetSymbolAddress((void**)&fb,  g_f_bf);
    cudaGetSymbolAddress((void**)&wib, g_wi_bf);
    cudaGetSymbolAddress((void**)&wob, g_wo_bf);

    static bool attr_set = false;
    if (!attr_set) {
        cudaFuncSetAttribute((const void*)mma_gemm_kernel<false, true>,
                             cudaFuncAttributeMaxDynamicSharedMemorySize, GEMM_SMEM);
        cudaFuncSetAttribute((const void*)mma_gemm_kernel<true, false>,
                             cudaFuncAttributeMaxDynamicSharedMemorySize, GEMM_SMEM);
        attr_set = true;
    }

    // 0) prep: x, W_in, W_out -> bf16
    prep_kernel<<<PREP_THREADS / 256, 256>>>(x, xb, W_in, wib, W_out, wob);

    // 1) h = x @ W_in^T  (bf16 out)
    {
        dim3 grid(PD / GBN, MT / GBM);   // 8 x 32 = 256 CTAs, 2/SM
        mma_gemm_kernel<false, true><<<grid, 256, GEMM_SMEM>>>(
            xb, wib, nullptr, hb, nullptr, nullptr);
    }

    // 2) softmax + gather-fuse -> bf16 fused (one kernel)
    fuse_kernel<<<PS, 128>>>(hb, routes, dist, fb);

    // 3) out = fused @ W_out^T + b_out + x
    {
        dim3 grid(PD / GBN, MT / GBM);
        mma_gemm_kernel<true, false><<<grid, 256, GEMM_SMEM>>>(
            fb, wob, out, nullptr, b_out, x);
    }
}